// round 7
// baseline (speedup 1.0000x reference)
#include <cuda_runtime.h>
#include <cstdint>

// ---------------------------------------------------------------------------
// Paillier decryption, CRT-factored via tiny shared-memory lookup tables.
//
//   n = 3599 = 59*61, n^2 = 12,952,801 = 3481 * 3721 (= p^2 * q^2, coprime)
//   lambda = lcm(58,60) = 1740, mu = 1740^{-1} mod 3599 = 1119
//   r = c^1740 mod n^2 via CRT:  r_p = (c mod 3481)^1740 mod 3481,
//   r_q likewise mod 3721; Garner: t=(r_q-r_p)*inv(3481) mod 3721 (inv=1876),
//   r = r_p + 3481*t.
//   m = (floor((r-1)/n) * mu) mod n = (((r + n^2 - 1)/n) * mu) mod n
//   out = relu( float(m) * (inv_scale / 1000) )
//
// R7: fused single kernel (R6) but with R5's winning shape restored:
// 256-thread blocks, 1184 persistent blocks, __launch_bounds__(256,8) to pin
// regs<=32 (R6's 512-thr/64-reg build halved occupancy and regressed).
// ---------------------------------------------------------------------------

#define P2 3481u
#define Q2 3721u
#define NN 3599u
#define N2 12952801u
#define MU 1119u
#define INV_P2_MOD_Q2 1876u

template <uint32_t MOD>
__device__ __forceinline__ uint32_t powmod_lambda(uint32_t b) {
    // exponent 1740 = 0b11011001100 (11 bits); all products < 3721^2 < 2^24
    uint32_t r = 1u;
    uint32_t e = 1740u;
    #pragma unroll
    for (int i = 0; i < 11; i++) {
        if (e & 1u) r = (r * b) % MOD;
        b = (b * b) % MOD;
        e >>= 1u;
    }
    return r;
}

__device__ __forceinline__ float dec_one(uint32_t cv, const uint32_t* sP,
                                         const uint16_t* sA, float s) {
    uint32_t xp = cv % P2;
    uint32_t yq = cv % Q2;
    uint32_t pw = sP[xp];
    uint32_t a  = (uint32_t)sA[yq];
    uint32_t rp = pw & 0xFFFFu;
    uint32_t t  = a + (pw >> 16);          // < 2*Q2
    t = umin(t, t - Q2);                   // cond-sub via unsigned wrap
    uint32_t r = rp + P2 * t;              // r = c^lambda mod n^2, < n^2
    uint32_t u = r + (N2 - 1u);            // < 2^25
    uint32_t q = u / NN;                   // magic-number division
    uint32_t m = (q * MU) % NN;            // q*MU < 2^23
    return fmaxf((float)m * s, 0.0f);
}

// Load 8 consecutive elements starting at element index o (multiple of 8).
template <int MODE>
__device__ __forceinline__ void load8(const void* in, uint32_t o, uint32_t cv[8]) {
    if (MODE == 1) {                        // int32
        uint4 a = __ldcs((const uint4*)in + (o >> 2));
        uint4 b = __ldcs((const uint4*)in + (o >> 2) + 1);
        cv[0]=a.x; cv[1]=a.y; cv[2]=a.z; cv[3]=a.w;
        cv[4]=b.x; cv[5]=b.y; cv[6]=b.z; cv[7]=b.w;
    } else if (MODE == 2) {                 // float32
        float4 a = __ldcs((const float4*)in + (o >> 2));
        float4 b = __ldcs((const float4*)in + (o >> 2) + 1);
        cv[0]=(uint32_t)a.x; cv[1]=(uint32_t)a.y; cv[2]=(uint32_t)a.z; cv[3]=(uint32_t)a.w;
        cv[4]=(uint32_t)b.x; cv[5]=(uint32_t)b.y; cv[6]=(uint32_t)b.z; cv[7]=(uint32_t)b.w;
    } else if (MODE == 0) {                 // int64 (values < 2^32 -> low words)
        const ulonglong2* p = (const ulonglong2*)in + (o >> 1);
        ulonglong2 a = __ldcs(p), b = __ldcs(p+1), c = __ldcs(p+2), d = __ldcs(p+3);
        cv[0]=(uint32_t)a.x; cv[1]=(uint32_t)a.y; cv[2]=(uint32_t)b.x; cv[3]=(uint32_t)b.y;
        cv[4]=(uint32_t)c.x; cv[5]=(uint32_t)c.y; cv[6]=(uint32_t)d.x; cv[7]=(uint32_t)d.y;
    } else {                                // double (integer-valued < 2^24)
        const double2* p = (const double2*)in + (o >> 1);
        double2 a = __ldcs(p), b = __ldcs(p+1), c = __ldcs(p+2), d = __ldcs(p+3);
        cv[0]=(uint32_t)__double2ll_rn(a.x); cv[1]=(uint32_t)__double2ll_rn(a.y);
        cv[2]=(uint32_t)__double2ll_rn(b.x); cv[3]=(uint32_t)__double2ll_rn(b.y);
        cv[4]=(uint32_t)__double2ll_rn(c.x); cv[5]=(uint32_t)__double2ll_rn(c.y);
        cv[6]=(uint32_t)__double2ll_rn(d.x); cv[7]=(uint32_t)__double2ll_rn(d.y);
    }
}

template <int MODE>
__device__ __forceinline__ void run_loop(const void* in, float* out, uint32_t n,
                                         const uint32_t* sP, const uint16_t* sA,
                                         float s) {
    const uint32_t nocts  = n >> 3;
    const uint32_t stride = gridDim.x * blockDim.x;
    for (uint32_t g = blockIdx.x * blockDim.x + threadIdx.x;
         g < nocts; g += stride) {
        uint32_t o = g << 3;
        uint32_t cv[8];
        load8<MODE>(in, o, cv);
        float4 lo, hi;
        lo.x = dec_one(cv[0], sP, sA, s);
        lo.y = dec_one(cv[1], sP, sA, s);
        lo.z = dec_one(cv[2], sP, sA, s);
        lo.w = dec_one(cv[3], sP, sA, s);
        hi.x = dec_one(cv[4], sP, sA, s);
        hi.y = dec_one(cv[5], sP, sA, s);
        hi.z = dec_one(cv[6], sP, sA, s);
        hi.w = dec_one(cv[7], sP, sA, s);
        __stcs((float4*)out + (o >> 2),     lo);
        __stcs((float4*)out + (o >> 2) + 1, hi);
    }
    // Scalar tail (n % 8 != 0)
    uint32_t tail = nocts << 3;
    uint32_t ti = tail + blockIdx.x * blockDim.x + threadIdx.x;
    if (blockIdx.x == 0 && ti < n) {
        uint32_t cv;
        if (MODE == 0)      cv = (uint32_t)((const unsigned long long*)in)[ti];
        else if (MODE == 1) cv = ((const uint32_t*)in)[ti];
        else if (MODE == 2) cv = (uint32_t)((const float*)in)[ti];
        else                cv = (uint32_t)((const double*)in)[ti];
        out[ti] = dec_one(cv, sP, sA, s);
    }
}

__global__ __launch_bounds__(256, 8) void paillier_dec_kernel(
    const void* __restrict__ in,
    const float* __restrict__ inv_scale,
    float* __restrict__ out,
    uint32_t n)
{
    __shared__ uint32_t sP[3481];
    __shared__ uint16_t sA[3721];
    __shared__ int sMode;

    // Build lookup tables locally (compile-time moduli -> cheap magic mods).
    for (uint32_t i = threadIdx.x; i < 3481u; i += 256u) {
        uint32_t rp = powmod_lambda<P2>(i);
        uint32_t bq = (Q2 - (rp * INV_P2_MOD_Q2) % Q2) % Q2;
        sP[i] = rp | (bq << 16);
    }
    for (uint32_t i = threadIdx.x; i < 3721u; i += 256u) {
        uint32_t aq = (powmod_lambda<Q2>(i) * INV_P2_MOD_Q2) % Q2;
        sA[i] = (uint16_t)aq;
    }

    // Layout probe from first 64 words (thread 0; overlaps table build).
    if (threadIdx.x == 0) {
        const uint32_t* w = (const uint32_t*)in;
        bool odd_zero = true, all_small = true, dbl_exp = true, even_low29 = true;
        #pragma unroll
        for (int k = 0; k < 64; k++) {
            uint32_t v = __ldg(w + k);
            if (k & 1) {
                if (v != 0u) odd_zero = false;
                uint32_t e = (v >> 20) & 0x7FFu;
                if (e < 0x3FFu || e > 0x416u) dbl_exp = false;
            } else {
                if (v & 0x1FFFFFFFu) even_low29 = false;
            }
            if (v >= 0x01000000u) all_small = false;
        }
        int mode;
        if (odd_zero)                   mode = 0;   // int64
        else if (all_small)             mode = 1;   // int32
        else if (dbl_exp && even_low29) mode = 3;   // double
        else                            mode = 2;   // float32
        sMode = mode;
    }
    __syncthreads();

    const float s = inv_scale[0] / 1000.0f;
    switch (sMode) {                       // uniform per block
        case 0: run_loop<0>(in, out, n, sP, sA, s); break;
        case 1: run_loop<1>(in, out, n, sP, sA, s); break;
        case 2: run_loop<2>(in, out, n, sP, sA, s); break;
        default: run_loop<3>(in, out, n, sP, sA, s); break;
    }
}

extern "C" void kernel_launch(void* const* d_in, const int* in_sizes, int n_in,
                              void* d_out, int out_size) {
    // Identify inputs by size: ciphertext tensor is huge, inv_scale is 1 elem.
    int ci = 0, si = 1;
    if (n_in >= 2 && in_sizes[0] <= 1) { ci = 1; si = 0; }
    const void* c        = d_in[ci];
    const float* inv_scl = (const float*)d_in[si];
    float* out           = (float*)d_out;
    uint32_t n = (uint32_t)out_size;   // output element count is unambiguous

    // Persistent: 148 SMs x 8 blocks x 256 threads (64 warps/SM).
    paillier_dec_kernel<<<148 * 8, 256>>>(c, inv_scl, out, n);
}

// round 8
// speedup vs baseline: 1.4028x; 1.4028x over previous
#include <cuda_runtime.h>
#include <cstdint>

// ---------------------------------------------------------------------------
// Paillier decryption, CRT-factored via tiny shared-memory lookup tables.
//
//   n = 3599 = 59*61, n^2 = 12,952,801 = 3481 * 3721 (= p^2 * q^2, coprime)
//   lambda = lcm(58,60) = 1740, mu = 1740^{-1} mod 3599 = 1119
//   r = c^1740 mod n^2 via CRT:  r_p = (c mod 3481)^1740 mod 3481,
//   r_q likewise mod 3721; Garner: t=(r_q-r_p)*inv(3481) mod 3721 (inv=1876),
//   r = r_p + 3481*t.
//   m = (floor((r-1)/n) * mu) mod n = (((r + n^2 - 1)/n) * mu) mod n
//   out = relu( float(m) * (inv_scale / 1000) )
//
// R8: reclaim R5's winning structure (setup kernel builds global tables +
// probes layout ONCE; hot blocks stage 21KB from L2). The R6/R7 in-kernel
// table build added ~1.1G prologue instructions (~22us) — removed. Kept from
// R6: uint32 hot-loop indexing, branchless cond-sub.
// ---------------------------------------------------------------------------

#define P2 3481u
#define Q2 3721u
#define NN 3599u
#define N2 12952801u
#define MU 1119u
#define INV_P2_MOD_Q2 1876u

__device__ uint32_t g_Ptab[3481];
__device__ uint16_t g_Atab[3721];
__device__ int g_mode;   // 0=int64, 1=int32, 2=float32, 3=double

template <uint32_t MOD>
__device__ __forceinline__ uint32_t powmod_lambda(uint32_t b) {
    // exponent 1740 = 0b11011001100 (11 bits); all products < 3721^2 < 2^24
    uint32_t r = 1u;
    uint32_t e = 1740u;
    #pragma unroll
    for (int i = 0; i < 11; i++) {
        if (e & 1u) r = (r * b) % MOD;
        b = (b * b) % MOD;
        e >>= 1u;
    }
    return r;
}

__global__ void setup_kernel(const uint32_t* __restrict__ w) {
    int i = blockIdx.x * blockDim.x + threadIdx.x;
    if (i < 3481) {
        uint32_t rp = powmod_lambda<P2>((uint32_t)i);
        uint32_t bq = (Q2 - (rp * INV_P2_MOD_Q2) % Q2) % Q2;
        g_Ptab[i] = rp | (bq << 16);
    } else if (i < 3481 + 3721) {
        uint32_t y  = (uint32_t)(i - 3481);
        uint32_t aq = (powmod_lambda<Q2>(y) * INV_P2_MOD_Q2) % Q2;
        g_Atab[y] = (uint16_t)aq;
    } else if (i == 3481 + 3721) {
        // Layout probe: classify the input buffer's element encoding.
        bool odd_zero   = true;   // int64: high halves all 0
        bool all_small  = true;   // int32: every word < 2^24
        bool dbl_exp    = true;   // double: hi-word exponent in [0x3FF,0x416]
        bool even_low29 = true;   // double: integer<2^24 -> low 29 bits clear
        #pragma unroll
        for (int k = 0; k < 64; k++) {
            uint32_t v = w[k];
            if (k & 1) {
                if (v != 0u) odd_zero = false;
                uint32_t e = (v >> 20) & 0x7FFu;
                if (e < 0x3FFu || e > 0x416u) dbl_exp = false;
            } else {
                if (v & 0x1FFFFFFFu) even_low29 = false;
            }
            if (v >= 0x01000000u) all_small = false;
        }
        int mode;
        if (odd_zero)                   mode = 0;   // int64
        else if (all_small)             mode = 1;   // int32
        else if (dbl_exp && even_low29) mode = 3;   // double
        else                            mode = 2;   // float32
        g_mode = mode;
    }
}

__device__ __forceinline__ float dec_one(uint32_t cv, const uint32_t* sP,
                                         const uint16_t* sA, float s) {
    uint32_t xp = cv % P2;
    uint32_t yq = cv % Q2;
    uint32_t pw = sP[xp];
    uint32_t a  = (uint32_t)sA[yq];
    uint32_t rp = pw & 0xFFFFu;
    uint32_t t  = a + (pw >> 16);          // < 2*Q2
    t = umin(t, t - Q2);                   // branchless cond-sub
    uint32_t r = rp + P2 * t;              // r = c^lambda mod n^2, < n^2
    uint32_t u = r + (N2 - 1u);            // < 2^25
    uint32_t q = u / NN;                   // magic-number division
    uint32_t m = (q * MU) % NN;            // q*MU < 2^23
    return fmaxf((float)m * s, 0.0f);
}

// Load 8 consecutive elements starting at element index o (multiple of 8).
template <int MODE>
__device__ __forceinline__ void load8(const void* in, uint32_t o, uint32_t cv[8]) {
    if (MODE == 1) {                        // int32
        uint4 a = __ldcs((const uint4*)in + (o >> 2));
        uint4 b = __ldcs((const uint4*)in + (o >> 2) + 1);
        cv[0]=a.x; cv[1]=a.y; cv[2]=a.z; cv[3]=a.w;
        cv[4]=b.x; cv[5]=b.y; cv[6]=b.z; cv[7]=b.w;
    } else if (MODE == 2) {                 // float32
        float4 a = __ldcs((const float4*)in + (o >> 2));
        float4 b = __ldcs((const float4*)in + (o >> 2) + 1);
        cv[0]=(uint32_t)a.x; cv[1]=(uint32_t)a.y; cv[2]=(uint32_t)a.z; cv[3]=(uint32_t)a.w;
        cv[4]=(uint32_t)b.x; cv[5]=(uint32_t)b.y; cv[6]=(uint32_t)b.z; cv[7]=(uint32_t)b.w;
    } else if (MODE == 0) {                 // int64 (values < 2^32 -> low words)
        const ulonglong2* p = (const ulonglong2*)in + (o >> 1);
        ulonglong2 a = __ldcs(p), b = __ldcs(p+1), c = __ldcs(p+2), d = __ldcs(p+3);
        cv[0]=(uint32_t)a.x; cv[1]=(uint32_t)a.y; cv[2]=(uint32_t)b.x; cv[3]=(uint32_t)b.y;
        cv[4]=(uint32_t)c.x; cv[5]=(uint32_t)c.y; cv[6]=(uint32_t)d.x; cv[7]=(uint32_t)d.y;
    } else {                                // double (integer-valued < 2^24)
        const double2* p = (const double2*)in + (o >> 1);
        double2 a = __ldcs(p), b = __ldcs(p+1), c = __ldcs(p+2), d = __ldcs(p+3);
        cv[0]=(uint32_t)__double2ll_rn(a.x); cv[1]=(uint32_t)__double2ll_rn(a.y);
        cv[2]=(uint32_t)__double2ll_rn(b.x); cv[3]=(uint32_t)__double2ll_rn(b.y);
        cv[4]=(uint32_t)__double2ll_rn(c.x); cv[5]=(uint32_t)__double2ll_rn(c.y);
        cv[6]=(uint32_t)__double2ll_rn(d.x); cv[7]=(uint32_t)__double2ll_rn(d.y);
    }
}

template <int MODE>
__device__ __forceinline__ void run_loop(const void* in, float* out, uint32_t n,
                                         const uint32_t* sP, const uint16_t* sA,
                                         float s) {
    const uint32_t nocts  = n >> 3;
    const uint32_t stride = gridDim.x * blockDim.x;
    for (uint32_t g = blockIdx.x * blockDim.x + threadIdx.x;
         g < nocts; g += stride) {
        uint32_t o = g << 3;
        uint32_t cv[8];
        load8<MODE>(in, o, cv);
        float4 lo, hi;
        lo.x = dec_one(cv[0], sP, sA, s);
        lo.y = dec_one(cv[1], sP, sA, s);
        lo.z = dec_one(cv[2], sP, sA, s);
        lo.w = dec_one(cv[3], sP, sA, s);
        hi.x = dec_one(cv[4], sP, sA, s);
        hi.y = dec_one(cv[5], sP, sA, s);
        hi.z = dec_one(cv[6], sP, sA, s);
        hi.w = dec_one(cv[7], sP, sA, s);
        __stcs((float4*)out + (o >> 2),     lo);
        __stcs((float4*)out + (o >> 2) + 1, hi);
    }
    // Scalar tail (n % 8 != 0)
    uint32_t tail = nocts << 3;
    uint32_t ti = tail + blockIdx.x * blockDim.x + threadIdx.x;
    if (blockIdx.x == 0 && ti < n) {
        uint32_t cv;
        if (MODE == 0)      cv = (uint32_t)((const unsigned long long*)in)[ti];
        else if (MODE == 1) cv = ((const uint32_t*)in)[ti];
        else if (MODE == 2) cv = (uint32_t)((const float*)in)[ti];
        else                cv = (uint32_t)((const double*)in)[ti];
        out[ti] = dec_one(cv, sP, sA, s);
    }
}

__global__ __launch_bounds__(256) void paillier_dec_kernel(
    const void* __restrict__ in,
    const float* __restrict__ inv_scale,
    float* __restrict__ out,
    uint32_t n)
{
    __shared__ uint32_t sP[3481];
    __shared__ uint16_t sA[3721];
    for (int i = threadIdx.x; i < 3481; i += 256) sP[i] = g_Ptab[i];
    for (int i = threadIdx.x; i < 3721; i += 256) sA[i] = g_Atab[i];
    __syncthreads();

    const float s = inv_scale[0] / 1000.0f;
    switch (g_mode) {                      // uniform across the grid
        case 0: run_loop<0>(in, out, n, sP, sA, s); break;
        case 1: run_loop<1>(in, out, n, sP, sA, s); break;
        case 2: run_loop<2>(in, out, n, sP, sA, s); break;
        default: run_loop<3>(in, out, n, sP, sA, s); break;
    }
}

extern "C" void kernel_launch(void* const* d_in, const int* in_sizes, int n_in,
                              void* d_out, int out_size) {
    // Identify inputs by size: ciphertext tensor is huge, inv_scale is 1 elem.
    int ci = 0, si = 1;
    if (n_in >= 2 && in_sizes[0] <= 1) { ci = 1; si = 0; }
    const void* c        = d_in[ci];
    const float* inv_scl = (const float*)d_in[si];
    float* out           = (float*)d_out;
    uint32_t n = (uint32_t)out_size;   // output element count is unambiguous

    setup_kernel<<<(3481 + 3721 + 1 + 255) / 256, 256>>>((const uint32_t*)c);

    // Persistent: 148 SMs x 8 blocks x 256 threads (64 warps/SM).
    paillier_dec_kernel<<<148 * 8, 256>>>(c, inv_scl, out, n);
}